// round 17
// baseline (speedup 1.0000x reference)
#include <cuda_runtime.h>
#include <cuda_fp16.h>
#include <cstdint>

// ============================================================================
// X[16,4096,256] -> proj(256->128)+bp -> relu(W1+b1) -> W2+b2 = Y
// out[b,n,:] = sum_m Y[b,m,:] - Y[b,n,:]
// R17: GEMM1 A-fragments loaded DIRECTLY from global X (coalesced LDG.64,
// no X smem buffers, no X prologue wait). SMEM ~101KB -> 2 CTAs/SM.
// H1/H2 share one fp16@272 buffer (pair-barriers around the swap).
// Weights: 2 x 32KB double buffer, 4 chunk regions (R16 schedule).
// Column sums fused into the final epilogue -> g_part[tile][128].
// ============================================================================

__device__ __align__(16) uint32_t g_wpack[8 * 4096];  // packed fp16 weights (128KB)
__device__ float g_part[512 * 128];

// ---------------- helpers ----------------
__device__ __forceinline__ uint32_t smem_u32(const void* p) {
    uint32_t a;
    asm("{ .reg .u64 t; cvta.to.shared.u64 t, %1; cvt.u32.u64 %0, t; }" : "=r"(a) : "l"(p));
    return a;
}
__device__ __forceinline__ void lds64f(uint32_t a, float& x, float& y) {
    asm volatile("ld.shared.v2.f32 {%0,%1}, [%2];" : "=f"(x), "=f"(y) : "r"(a));
}
__device__ __forceinline__ void lds128u(uint32_t a, uint32_t& x, uint32_t& y, uint32_t& z, uint32_t& w) {
    asm volatile("ld.shared.v4.b32 {%0,%1,%2,%3}, [%4];" : "=r"(x), "=r"(y), "=r"(z), "=r"(w) : "r"(a));
}
__device__ __forceinline__ void sts32u(uint32_t a, uint32_t v) {
    asm volatile("st.shared.b32 [%0], %1;" :: "r"(a), "r"(v));
}
__device__ __forceinline__ uint32_t packh2(float lo, float hi) {
    uint32_t u;
    asm("cvt.rn.f16x2.f32 %0, %1, %2;" : "=r"(u) : "f"(hi), "f"(lo));
    return u;
}
__device__ __forceinline__ void ldmA4(uint32_t a, uint32_t* r) {
    asm volatile("ldmatrix.sync.aligned.m8n8.x4.shared.b16 {%0,%1,%2,%3}, [%4];"
        : "=r"(r[0]), "=r"(r[1]), "=r"(r[2]), "=r"(r[3]) : "r"(a));
}
__device__ __forceinline__ void mma16(float* d,
                                      uint32_t a0, uint32_t a1, uint32_t a2, uint32_t a3,
                                      uint32_t b0, uint32_t b1) {
    asm volatile(
        "mma.sync.aligned.m16n8k16.row.col.f32.f16.f16.f32 "
        "{%0,%1,%2,%3}, {%4,%5,%6,%7}, {%8,%9}, {%0,%1,%2,%3};"
        : "+f"(d[0]), "+f"(d[1]), "+f"(d[2]), "+f"(d[3])
        : "r"(a0), "r"(a1), "r"(a2), "r"(a3), "r"(b0), "r"(b1));
}
#define CP16(dst, src)  asm volatile("cp.async.cg.shared.global [%0], [%1], 16;" :: "r"(dst), "l"(src))
#define CP_COMMIT()     asm volatile("cp.async.commit_group;" ::: "memory")
#define CP_WAIT(n)      asm volatile("cp.async.wait_group %0;" :: "n"(n) : "memory")
#define BAR64(id)       asm volatile("bar.sync %0, 64;" :: "r"(id) : "memory")

// ============================================================================
// prep: pack weights (fp16) into lane-ordered quad layout (proven R4-R16).
// 16KB sub-chunk c (0..7) covers 64 k-rows x 128 n (0-3:Wp, 4-5:W1, 6-7:W2).
// uint32 idx within sub-chunk: ((ks*8+bp)*32 + lane)*4 + q, where
//   k_local = ks*16 + (q&1)*8 + (lane&3)*2 ; n = bp*16 + (q>>1)*8 + (lane>>2)
// ============================================================================
__global__ void prep_kernel(const float* __restrict__ Wp,
                            const float* __restrict__ W1,
                            const float* __restrict__ W2) {
    int i = blockIdx.x * 256 + threadIdx.x;          // 32768 total
    int chunk = i >> 12;
    int within = i & 4095;
    int q = within & 3, ln = (within >> 2) & 31, bpks = within >> 7;
    int bpi = bpks & 7, ks = bpks >> 3;
    int kl = ks * 16 + (q & 1) * 8 + (ln & 3) * 2;
    int n = bpi * 16 + (q >> 1) * 8 + (ln >> 2);
    const float* W;
    int krow;
    if (chunk < 4)      { W = Wp; krow = chunk * 64 + kl; }
    else if (chunk < 6) { W = W1; krow = (chunk - 4) * 64 + kl; }
    else                { W = W2; krow = (chunk - 6) * 64 + kl; }
    float w0 = W[(size_t)krow * 128 + n];
    float w1 = W[(size_t)(krow + 1) * 128 + n];
    g_wpack[i] = packh2(w0, w1);
}

// ============================================================================
// fused kernel — ~101.5KB SMEM, 256 threads (8 warps), 2 CTAs/SM.
// ============================================================================
#define SM_H    0                     // 128*272 = 34816 (H1 then H2, fp16)
#define SM_W0   34816                 // 32KB weight buffer 0
#define SM_W1B  67584                 // 32KB weight buffer 1
#define SM_BIAS 100352                // bp[128], b1[128], b2[128] (f32)
#define SM_RED  101888                // 4*128 floats
#define SMEM_SZ 103936

// GEMM1 chunk: A-fragments DIRECT from global X (coalesced LDG.64).
// p0 = &X[row=gr][col=(l&3)*2] for this half, as float2 (row stride 128 f2).
__device__ __forceinline__ void gemm1_ldg(const float2* __restrict__ p0,
                                          uint32_t wb, int nh, int l, float acc[2][8][4]) {
    #pragma unroll
    for (int ks = 0; ks < 8; ++ks) {
        uint32_t A[2][4];
        const float2* q = p0 + ks * 8;
        #pragma unroll
        for (int mb = 0; mb < 2; ++mb) {
            const float2* r = q + mb * (16 * 128);
            float2 x0 = r[0];             // row,   k pair
            float2 y0 = r[8 * 128];       // row+8, k pair
            float2 x1 = r[4];             // row,   k+8 pair
            float2 y1 = r[8 * 128 + 4];   // row+8, k+8 pair
            A[mb][0] = packh2(x0.x, x0.y);
            A[mb][1] = packh2(y0.x, y0.y);
            A[mb][2] = packh2(x1.x, x1.y);
            A[mb][3] = packh2(y1.x, y1.y);
        }
        uint32_t bb = wb + (uint32_t)((ks >> 2) * 16384 + (ks & 3) * 4096)
                         + (uint32_t)(nh * 4) * 512 + (uint32_t)l * 16;
        #pragma unroll
        for (int bpi = 0; bpi < 4; ++bpi) {
            uint32_t q0, q1, q2, q3;
            lds128u(bb + (uint32_t)bpi * 512, q0, q1, q2, q3);
            mma16(acc[0][2 * bpi],     A[0][0], A[0][1], A[0][2], A[0][3], q0, q1);
            mma16(acc[1][2 * bpi],     A[1][0], A[1][1], A[1][2], A[1][3], q0, q1);
            mma16(acc[0][2 * bpi + 1], A[0][0], A[0][1], A[0][2], A[0][3], q2, q3);
            mma16(acc[1][2 * bpi + 1], A[1][0], A[1][1], A[1][2], A[1][3], q2, q3);
        }
    }
}

// 32KB chunk, fp16 ldmatrix A-path (GEMM2/3): H stride 272.
__device__ __forceinline__ void gemm_chunk_h16(uint32_t a_lane, uint32_t wb,
                                               int nh, int l, float acc[2][8][4]) {
    #pragma unroll
    for (int ks = 0; ks < 8; ++ks) {
        uint32_t A0[4], A1[4];
        uint32_t aa = a_lane + (uint32_t)ks * 32;
        ldmA4(aa, A0);
        ldmA4(aa + 16 * 272, A1);
        uint32_t bb = wb + (uint32_t)((ks >> 2) * 16384 + (ks & 3) * 4096)
                         + (uint32_t)(nh * 4) * 512 + (uint32_t)l * 16;
        #pragma unroll
        for (int bpi = 0; bpi < 4; ++bpi) {
            uint32_t q0, q1, q2, q3;
            lds128u(bb + (uint32_t)bpi * 512, q0, q1, q2, q3);
            mma16(acc[0][2 * bpi],     A0[0], A0[1], A0[2], A0[3], q0, q1);
            mma16(acc[1][2 * bpi],     A1[0], A1[1], A1[2], A1[3], q0, q1);
            mma16(acc[0][2 * bpi + 1], A0[0], A0[1], A0[2], A0[3], q2, q3);
            mma16(acc[1][2 * bpi + 1], A1[0], A1[1], A1[2], A1[3], q2, q3);
        }
    }
}

__global__ void __launch_bounds__(256, 2) fused_kernel(
    const float* __restrict__ X,
    const float* __restrict__ bp,
    const float* __restrict__ b1,
    const float* __restrict__ b2,
    float* __restrict__ out)
{
    extern __shared__ char smem[];
    const uint32_t sb = smem_u32(smem);
    const int tid = threadIdx.x;
    const int l = tid & 31;
    const int w = tid >> 5;
    const int wrow = (w >> 1) * 32;        // row group (32 rows per warp)
    const int nh = w & 1;                  // n-half
    const int t = blockIdx.x;

    // prologue: g0 = Wp0 -> W0 ; g1 = Wp1 -> W1B (no X staging at all)
    #pragma unroll
    for (int h = 0; h < 2; ++h) {
        uint32_t bdst = sb + (h ? SM_W1B : SM_W0);
        const uint4* ws = (const uint4*)(g_wpack + h * 8192);
        for (int i = tid; i < 2048; i += 256) CP16(bdst + i * 16, ws + i);
        CP_COMMIT();
    }
    if (tid < 128) {
        ((float*)(smem + SM_BIAS))[tid]       = bp[tid];
        ((float*)(smem + SM_BIAS))[128 + tid] = b1[tid];
        ((float*)(smem + SM_BIAS))[256 + tid] = b2[tid];
    }

    float acc[2][8][4];
    #pragma unroll
    for (int m = 0; m < 2; ++m)
        #pragma unroll
        for (int nb = 0; nb < 8; ++nb)
            #pragma unroll
            for (int k = 0; k < 4; ++k) acc[m][nb][k] = 0.f;

    // direct-LDG A base: row gr, col (l&3)*2 (float2 units; row stride 128 f2)
    const float2* xrow = (const float2*)(X + ((size_t)t * 128 + wrow + (l >> 2)) * 256
                                           + (size_t)(l & 3) * 2);
    const uint32_t lmrow = ((uint32_t)wrow + (uint32_t)(l & 15)) * 272 + (uint32_t)(l >> 4) * 16;
    const uint32_t aH = sb + SM_H + lmrow;

    // ---- ch0: Wp[k<128] x Xh0 (A direct from global) ----
    CP_WAIT(1);            // g0 (Wp0) done
    __syncthreads();       // barrier #1
    gemm1_ldg(xrow, sb + SM_W0, nh, l, acc);
    __syncthreads();       // barrier #2: W0buf ch0 reads done

    // prefetch W1 -> W0buf (g2), overlapped with ch1
    {
        const uint4* ws = (const uint4*)(g_wpack + 2 * 8192);
        for (int i = tid; i < 2048; i += 256) CP16(sb + SM_W0 + i * 16, ws + i);
        CP_COMMIT();
    }

    // ---- ch1: Wp[k>=128] x Xh1 (accumulate), then epi1 ----
    CP_WAIT(1);            // g1 (Wp1) done; g2 in flight
    gemm1_ldg(xrow + 64, sb + SM_W1B, nh, l, acc);

    // epi1: H1 = acc + bp -> SM_H (first write to H; no prior readers)
    {
        const uint32_t bo = sb + SM_BIAS + (uint32_t)nh * 256;
        #pragma unroll
        for (int nb = 0; nb < 8; ++nb) {
            float bx, by;
            lds64f(bo + (uint32_t)(nb * 8 + (l & 3) * 2) * 4, bx, by);
            #pragma unroll
            for (int mb = 0; mb < 2; ++mb) {
                float v0 = acc[mb][nb][0] + bx, v1 = acc[mb][nb][1] + by;
                float v2 = acc[mb][nb][2] + bx, v3 = acc[mb][nb][3] + by;
                uint32_t sa = sb + SM_H + (uint32_t)(wrow + mb * 16 + (l >> 2)) * 272
                                        + (uint32_t)(nh * 64 + nb * 8 + (l & 3) * 2) * 2;
                sts32u(sa, packh2(v0, v1));
                sts32u(sa + 8 * 272, packh2(v2, v3));
                acc[mb][nb][0] = 0.f; acc[mb][nb][1] = 0.f;
                acc[mb][nb][2] = 0.f; acc[mb][nb][3] = 0.f;
            }
        }
    }
    __syncthreads();       // barrier #3: H1 visible; W1B ch1 reads done

    // prefetch W2 -> W1B (g3), overlapped with ch2
    {
        const uint4* ws = (const uint4*)(g_wpack + 3 * 8192);
        for (int i = tid; i < 2048; i += 256) CP16(sb + SM_W1B + i * 16, ws + i);
        CP_COMMIT();
    }

    // ---- ch2: W1 x H1 ----
    CP_WAIT(1);            // g2 (W1) done; g3 in flight
    gemm_chunk_h16(aH, sb + SM_W0, nh, l, acc);

    BAR64(1 + (w >> 1));   // pair barrier: this rowgroup's H1 reads all done

    // epi2: H2 = relu(acc + b1) -> SM_H (same buffer, pair-local hazard only)
    {
        const uint32_t bo = sb + SM_BIAS + 512 + (uint32_t)nh * 256;
        #pragma unroll
        for (int nb = 0; nb < 8; ++nb) {
            float bx, by;
            lds64f(bo + (uint32_t)(nb * 8 + (l & 3) * 2) * 4, bx, by);
            #pragma unroll
            for (int mb = 0; mb < 2; ++mb) {
                float v0 = fmaxf(acc[mb][nb][0] + bx, 0.f);
                float v1 = fmaxf(acc[mb][nb][1] + by, 0.f);
                float v2 = fmaxf(acc[mb][nb][2] + bx, 0.f);
                float v3 = fmaxf(acc[mb][nb][3] + by, 0.f);
                uint32_t sa = sb + SM_H + (uint32_t)(wrow + mb * 16 + (l >> 2)) * 272
                                        + (uint32_t)(nh * 64 + nb * 8 + (l & 3) * 2) * 2;
                sts32u(sa, packh2(v0, v1));
                sts32u(sa + 8 * 272, packh2(v2, v3));
                acc[mb][nb][0] = 0.f; acc[mb][nb][1] = 0.f;
                acc[mb][nb][2] = 0.f; acc[mb][nb][3] = 0.f;
            }
        }
    }
    BAR64(1 + (w >> 1));   // pair barrier: H2 visible to this rowgroup pair

    // ---- ch3: W2 x H2, then final epilogue ----
    CP_WAIT(0);            // g3 (W2) done
    gemm_chunk_h16(aH, sb + SM_W1B, nh, l, acc);

    {
        const size_t rb = (size_t)t * 128 + wrow + (l >> 2);
        float cs[8][2];
        #pragma unroll
        for (int nb = 0; nb < 8; ++nb) { cs[nb][0] = 0.f; cs[nb][1] = 0.f; }
        #pragma unroll
        for (int nb = 0; nb < 8; ++nb) {
            float bx, by;
            lds64f(sb + SM_BIAS + 1024 + (uint32_t)(nh * 64 + nb * 8 + (l & 3) * 2) * 4, bx, by);
            #pragma unroll
            for (int mb = 0; mb < 2; ++mb) {
                float v0 = acc[mb][nb][0] + bx, v1 = acc[mb][nb][1] + by;
                float v2 = acc[mb][nb][2] + bx, v3 = acc[mb][nb][3] + by;
                size_t r0 = (rb + mb * 16) * 128 + nh * 64 + nb * 8 + (l & 3) * 2;
                *(float2*)(out + r0)           = make_float2(v0, v1);
                *(float2*)(out + r0 + 8 * 128) = make_float2(v2, v3);
                cs[nb][0] += v0 + v2;
                cs[nb][1] += v1 + v3;
            }
        }
        #pragma unroll
        for (int nb = 0; nb < 8; ++nb) {
            #pragma unroll
            for (int j = 0; j < 2; ++j) {
                float s = cs[nb][j];
                s += __shfl_down_sync(0xFFFFFFFFu, s, 16);
                s += __shfl_down_sync(0xFFFFFFFFu, s, 8);
                s += __shfl_down_sync(0xFFFFFFFFu, s, 4);
                if (l < 4)
                    ((float*)(smem + SM_RED))[(w >> 1) * 128 + nh * 64 + nb * 8 + l * 2 + j] = s;
            }
        }
    }
    __syncthreads();

    if (tid < 128) {
        const float* R = (const float*)(smem + SM_RED);
        g_part[(size_t)t * 128 + tid] = R[tid] + R[128 + tid] + R[256 + tid] + R[384 + tid];
    }
}

// ---------------- out = S - Y (in place, float4) ----------------
__global__ void subtract_kernel(float* __restrict__ out) {
    __shared__ float4 S4[32];
    int b = blockIdx.x, nc = blockIdx.y, tid = threadIdx.x;
    if (tid < 128) {
        float s = 0.f;
        const float* gp = g_part + (size_t)b * 32 * 128 + tid;
        #pragma unroll
        for (int c = 0; c < 32; ++c) s += gp[c * 128];
        ((float*)S4)[tid] = s;
    }
    __syncthreads();
    float4* p = (float4*)(out + ((size_t)b * 4096 + (size_t)nc * 128) * 128);
    for (int i = tid; i < 4096; i += 256) {
        float4 s = S4[i & 31];
        float4 v = p[i];
        p[i] = make_float4(s.x - v.x, s.y - v.y, s.z - v.z, s.w - v.w);
    }
}

// ---------------- launch ----------------
extern "C" void kernel_launch(void* const* d_in, const int* in_sizes, int n_in,
                              void* d_out, int out_size) {
    const float* X  = (const float*)d_in[0];
    const float* Wp = (const float*)d_in[1];
    const float* bp = (const float*)d_in[2];
    const float* W1 = (const float*)d_in[3];
    const float* b1 = (const float*)d_in[4];
    const float* W2 = (const float*)d_in[5];
    const float* b2 = (const float*)d_in[6];
    float* out = (float*)d_out;

    cudaFuncSetAttribute(fused_kernel,
                         cudaFuncAttributeMaxDynamicSharedMemorySize, SMEM_SZ);

    prep_kernel<<<128, 256>>>(Wp, W1, W2);
    fused_kernel<<<512, 256, SMEM_SZ>>>(X, bp, b1, b2, out);
    subtract_kernel<<<dim3(16, 32), 256>>>(out);
}